// round 12
// baseline (speedup 1.0000x reference)
#include <cuda_runtime.h>
#include <math.h>

// Problem constants
#define BV 64
#define TV 128
#define LV 40
#define EV 64
#define NKV 200          // N*k
#define G4 256           // 4*E
#define SUPROWS (BV*NKV) // 12800
#define TGTROWS (BV*TV)  // 8192
#define KITERS 5
#define SP 68            // padded row stride for S / WH (16B aligned, conflict-free)
#define AP 202           // ATT row stride (keeps every row 8B-aligned for u64 loads)

// Scratch (device globals; no allocation allowed)
__device__ float g_sup_enc[SUPROWS*EV];
__device__ float g_tgt_enc[TGTROWS*EV];
__device__ float g_pre_gf[SUPROWS*G4];
__device__ float g_pre_gb[SUPROWS*G4];
__device__ float g_hf[SUPROWS*EV];
__device__ float g_hb[SUPROWS*EV];
__device__ float g_pre_x[TGTROWS*G4];

typedef unsigned long long u64t;

__device__ __forceinline__ u64t ffma2(u64t a, u64t b, u64t c) {
    u64t d;
    asm("fma.rn.f32x2 %0,%1,%2,%3;" : "=l"(d) : "l"(a), "l"(b), "l"(c));
    return d;
}
__device__ __forceinline__ u64t pack2(float lo, float hi) {
    u64t r;
    asm("mov.b64 %0,{%1,%2};" : "=l"(r) : "f"(lo), "f"(hi));
    return r;
}
__device__ __forceinline__ float hsum2(u64t v) {
    float lo, hi;
    asm("mov.b64 {%0,%1},%2;" : "=f"(lo), "=f"(hi) : "l"(v));
    return lo + hi;
}

__device__ __forceinline__ float sigf(float x) { return 1.0f / (1.0f + __expf(-x)); }
__device__ __forceinline__ float tanhfast(float x) {
    float a = fabsf(x);
    float t = __expf(-2.0f * a);
    float r = (1.0f - t) / (1.0f + t);
    return copysignf(r, x);
}

// ---------------------------------------------------------------------------
// Kernel 1: embedding gather-sums. 16 threads per row (float4 per thread).
// ---------------------------------------------------------------------------
__global__ __launch_bounds__(256) void embed_sum_kernel(
    const int* __restrict__ sup_tok,
    const int* __restrict__ tgt_tok,
    const float* __restrict__ emb)
{
    int row = blockIdx.x * 16 + (threadIdx.x >> 4);
    int e = (threadIdx.x & 15) * 4;
    const int* tok;
    float* out;
    if (row < SUPROWS) {
        tok = sup_tok + row * LV;
        out = g_sup_enc + row * EV;
    } else {
        int r2 = row - SUPROWS;
        tok = tgt_tok + r2 * LV;
        out = g_tgt_enc + r2 * EV;
    }
    float ax = 0.f, ay = 0.f, az = 0.f, aw = 0.f;
#pragma unroll 8
    for (int l = 0; l < LV; l++) {
        int t = tok[l];
        float4 v = *(const float4*)&emb[t * EV + e];
        ax += v.x; ay += v.y; az += v.z; aw += v.w;
    }
    float4 o; o.x = ax; o.y = ay; o.z = az; o.w = aw;
    *(float4*)&out[e] = o;
}

// ---------------------------------------------------------------------------
// Kernel 2 (merged): C[M,256] = A[M,64] @ W[256,64]^T + (b1+b2).
// W stored row-major W_sh[j][e] (pad 65): conflict-free fill AND compute.
// ---------------------------------------------------------------------------
__global__ __launch_bounds__(256, 2) void gemm_all_kernel(
    const float* __restrict__ sup_enc_g, const float* __restrict__ tgt_enc_g,
    const float* __restrict__ gf_W, const float* __restrict__ gf_b1, const float* __restrict__ gf_b2,
    const float* __restrict__ gb_W, const float* __restrict__ gb_b1, const float* __restrict__ gb_b2,
    const float* __restrict__ f_W,  const float* __restrict__ f_b1,  const float* __restrict__ f_b2,
    float* __restrict__ pre_gf, float* __restrict__ pre_gb, float* __restrict__ pre_x)
{
    __shared__ float A_sh[64][64];
    __shared__ float W_sh[256][65];
    __shared__ float bias_sh[256];

    int blk = blockIdx.x;
    const float *A, *W, *b1, *b2;
    float* C;
    int row0;
    if (blk < 200)      { A = sup_enc_g; W = gf_W; b1 = gf_b1; b2 = gf_b2; C = pre_gf; row0 = blk * 64; }
    else if (blk < 400) { A = sup_enc_g; W = gb_W; b1 = gb_b1; b2 = gb_b2; C = pre_gb; row0 = (blk - 200) * 64; }
    else                { A = tgt_enc_g; W = f_W;  b1 = f_b1;  b2 = f_b2;  C = pre_x;  row0 = (blk - 400) * 64; }

    int tid = threadIdx.x;
    int tx = tid & 31, ty = tid >> 5;

    for (int idx = tid; idx < 256 * 64; idx += 256) {
        int j = idx >> 6, e = idx & 63;
        W_sh[j][e] = W[idx];                  // row-major, coalesced, no conflicts
    }
    bias_sh[tid] = b1[tid] + b2[tid];
    for (int idx = tid; idx < 64 * 64; idx += 256) {
        A_sh[idx >> 6][idx & 63] = A[row0 * 64 + idx];
    }
    __syncthreads();

    float acc[8][8];
#pragma unroll
    for (int i = 0; i < 8; i++)
#pragma unroll
        for (int q = 0; q < 8; q++) acc[i][q] = 0.0f;

#pragma unroll 4
    for (int e = 0; e < 64; e++) {
        float a[8], bb[8];
#pragma unroll
        for (int i = 0; i < 8; i++) a[i] = A_sh[ty * 8 + i][e];       // broadcast
#pragma unroll
        for (int q = 0; q < 8; q++) bb[q] = W_sh[tx + 32 * q][e];     // (tx+e)%32 distinct
#pragma unroll
        for (int i = 0; i < 8; i++)
#pragma unroll
            for (int q = 0; q < 8; q++) acc[i][q] = fmaf(a[i], bb[q], acc[i][q]);
    }

#pragma unroll
    for (int i = 0; i < 8; i++) {
        int r = row0 + ty * 8 + i;
#pragma unroll
        for (int q = 0; q < 8; q++) {
            int j = tx + 32 * q;
            C[r * 256 + j] = acc[i][q] + bias_sh[j];
        }
    }
}

// ---------------------------------------------------------------------------
// Kernel 3: bidirectional LSTM (prefetch + 8 accumulators, chain depth 8).
// ---------------------------------------------------------------------------
__global__ __launch_bounds__(256) void lstm_kernel(
    const float* __restrict__ gf_Whh, const float* __restrict__ gb_Whh)
{
    int bx = blockIdx.x;
    int dir = bx & 1, b = bx >> 1;
    int tid = threadIdx.x;
    int L = tid & 31, w = tid >> 5;
    int ep = w * 8 + (L & 7);
    int gate = L >> 3;
    int j = gate * 64 + ep;

    const float* Whh = dir ? gb_Whh : gf_Whh;
    const float* pre = dir ? g_pre_gb : g_pre_gf;
    float* out = dir ? g_hb : g_hf;

    float wr[64];
#pragma unroll
    for (int e = 0; e < 64; e++) wr[e] = Whh[j * 64 + e];

    __shared__ __align__(16) float h_sh[2][64];
    if (tid < 64) h_sh[0][tid] = 0.0f;
    float c = 0.0f;
    __syncthreads();

    int srow_first = dir ? (NKV - 1) : 0;
    float z_next = pre[(b * NKV + srow_first) * 256 + j];

    int cur = 0;
    for (int s = 0; s < NKV; s++) {
        int srow = dir ? (NKV - 1 - s) : s;
        int row = b * NKV + srow;
        float z = z_next;
        if (s + 1 < NKV) {
            int nr = dir ? (NKV - 2 - s) : (s + 1);
            z_next = pre[(b * NKV + nr) * 256 + j];
        }

        const float4* h4 = (const float4*)h_sh[cur];
        float a0 = 0.f, a1 = 0.f, a2 = 0.f, a3 = 0.f;
        float b0 = 0.f, b1 = 0.f, b2 = 0.f, b3 = 0.f;
#pragma unroll
        for (int q = 0; q < 16; q += 2) {
            float4 hv0 = h4[q];
            float4 hv1 = h4[q + 1];
            a0 = fmaf(hv0.x, wr[4 * q + 0], a0);
            a1 = fmaf(hv0.y, wr[4 * q + 1], a1);
            a2 = fmaf(hv0.z, wr[4 * q + 2], a2);
            a3 = fmaf(hv0.w, wr[4 * q + 3], a3);
            b0 = fmaf(hv1.x, wr[4 * q + 4], b0);
            b1 = fmaf(hv1.y, wr[4 * q + 5], b1);
            b2 = fmaf(hv1.z, wr[4 * q + 6], b2);
            b3 = fmaf(hv1.w, wr[4 * q + 7], b3);
        }
        z += ((a0 + a1) + (a2 + a3)) + ((b0 + b1) + (b2 + b3));

        float zf = __shfl_down_sync(0xFFFFFFFFu, z, 8);
        float zg = __shfl_down_sync(0xFFFFFFFFu, z, 16);
        float zo = __shfl_down_sync(0xFFFFFFFFu, z, 24);
        if (L < 8) {
            c = sigf(zf) * c + sigf(z) * tanhfast(zg);
            float h = sigf(zo) * tanhfast(c);
            h_sh[cur ^ 1][ep] = h;
            out[row * 64 + ep] = h;
        }
        cur ^= 1;
        __syncthreads();
    }
}

// ---------------------------------------------------------------------------
// Kernel 4: fused K-hop attention + final cosine softmax.
// 512 threads, 16 warps x 4 target rows, __syncwarp-only inner flow.
// Scores scalar (register-light). Cell: f32x2 over e, two gate-halves to cap
// live accumulators at 32 regs. Readout: f32x2 over n-pairs with 8B broadcast
// ATT loads (stride AP=202 keeps every row 8B-aligned).
// ---------------------------------------------------------------------------
__global__ __launch_bounds__(512) void attn_kernel(
    const float* __restrict__ f_Whh, float* __restrict__ out)
{
    extern __shared__ float sm[];
    float* S   = sm;                      // [200][SP]
    float* WH  = S + 200 * SP;            // [256][SP]
    float* H   = WH + 256 * SP;           // [64][64]
    float* ATT = H + 64 * 64;             // [64][AP]
    float* SN  = ATT + 64 * AP;           // [200]

    int tid = threadIdx.x;
    int L = tid & 31, w = tid >> 5;       // w = 0..15
    int b = blockIdx.x >> 1, half = blockIdx.x & 1;
    int srow0 = b * NKV;
    int trow0 = b * TV + half * 64;

    for (int idx = tid; idx < NKV * 64; idx += 512) {
        int n = idx >> 6, e = idx & 63;
        int gr = (srow0 + n) * 64 + e;
        S[n * SP + e] = g_hf[gr] + g_hb[gr] + g_sup_enc[gr];
    }
    for (int idx = tid; idx < 256 * 64; idx += 512) {
        int j = idx >> 6, e = idx & 63;
        WH[j * SP + e] = f_Whh[idx];
    }
    for (int idx = tid; idx < 64 * 64; idx += 512) H[idx] = 0.0f;

    float x0[4], x1[4], r0[4], r1[4], c0[4], c1[4];
#pragma unroll
    for (int i = 0; i < 4; i++) {
        int grow = trow0 + w * 4 + i;
        x0[i] = g_tgt_enc[grow * 64 + L];
        x1[i] = g_tgt_enc[grow * 64 + 32 + L];
        r0[i] = r1[i] = c0[i] = c1[i] = 0.0f;
    }
    __syncthreads();

    int n6 = 192 + (L & 7);

    for (int iter = 0; iter < KITERS; iter++) {
        // h = h + r
#pragma unroll
        for (int i = 0; i < 4; i++) {
            int tl = w * 4 + i;
            H[tl * 64 + L]      += r0[i];
            H[tl * 64 + 32 + L] += r1[i];
        }
        __syncwarp();

        if (iter < KITERS - 1) {
            // ---- scores (scalar, register-light) ----
            float sc[4][7];
#pragma unroll
            for (int i = 0; i < 4; i++)
#pragma unroll
                for (int q = 0; q < 7; q++) sc[i][q] = 0.0f;

            for (int e = 0; e < 64; e += 4) {
                float4 a4[4];
#pragma unroll
                for (int i = 0; i < 4; i++)
                    a4[i] = *(const float4*)&H[(w * 4 + i) * 64 + e];
#pragma unroll
                for (int q = 0; q < 6; q++) {
                    float4 s4 = *(const float4*)&S[(L + 32 * q) * SP + e];
#pragma unroll
                    for (int i = 0; i < 4; i++) {
                        sc[i][q] = fmaf(a4[i].x, s4.x, sc[i][q]);
                        sc[i][q] = fmaf(a4[i].y, s4.y, sc[i][q]);
                        sc[i][q] = fmaf(a4[i].z, s4.z, sc[i][q]);
                        sc[i][q] = fmaf(a4[i].w, s4.w, sc[i][q]);
                    }
                }
                float4 s6 = *(const float4*)&S[n6 * SP + e];
#pragma unroll
                for (int i = 0; i < 4; i++) {
                    sc[i][6] = fmaf(a4[i].x, s6.x, sc[i][6]);
                    sc[i][6] = fmaf(a4[i].y, s6.y, sc[i][6]);
                    sc[i][6] = fmaf(a4[i].z, s6.z, sc[i][6]);
                    sc[i][6] = fmaf(a4[i].w, s6.w, sc[i][6]);
                }
            }

            // softmax over 200, write att to SMEM (stride AP)
#pragma unroll
            for (int i = 0; i < 4; i++) {
                float m = sc[i][0];
#pragma unroll
                for (int q = 1; q < 6; q++) m = fmaxf(m, sc[i][q]);
                float v6 = (L < 8) ? sc[i][6] : -1e30f;
                m = fmaxf(m, v6);
#pragma unroll
                for (int o = 16; o > 0; o >>= 1)
                    m = fmaxf(m, __shfl_xor_sync(0xFFFFFFFFu, m, o));
                float ex[7], ssum = 0.0f;
#pragma unroll
                for (int q = 0; q < 6; q++) { ex[q] = __expf(sc[i][q] - m); ssum += ex[q]; }
                ex[6] = (L < 8) ? __expf(sc[i][6] - m) : 0.0f;
                ssum += ex[6];
#pragma unroll
                for (int o = 16; o > 0; o >>= 1)
                    ssum += __shfl_xor_sync(0xFFFFFFFFu, ssum, o);
                float inv = 1.0f / ssum;
                int tl = w * 4 + i;
#pragma unroll
                for (int q = 0; q < 6; q++) ATT[tl * AP + L + 32 * q] = ex[q] * inv;
                if (L < 8) ATT[tl * AP + 192 + L] = ex[6] * inv;
            }
            __syncwarp();

            // ---- readout: f32x2 over n-pairs ----
            u64t r0p[4], r1p[4];
#pragma unroll
            for (int i = 0; i < 4; i++) { r0p[i] = 0ull; r1p[i] = 0ull; }
            for (int n = 0; n < NKV; n += 4) {
                u64t s0a = pack2(S[(n + 0) * SP + L],      S[(n + 1) * SP + L]);
                u64t s0b = pack2(S[(n + 2) * SP + L],      S[(n + 3) * SP + L]);
                u64t s1a = pack2(S[(n + 0) * SP + 32 + L], S[(n + 1) * SP + 32 + L]);
                u64t s1b = pack2(S[(n + 2) * SP + 32 + L], S[(n + 3) * SP + 32 + L]);
#pragma unroll
                for (int i = 0; i < 4; i++) {
                    const u64t* ap = (const u64t*)&ATT[(w * 4 + i) * AP + n];
                    u64t aa = ap[0], ab = ap[1];     // 8B broadcast loads
                    r0p[i] = ffma2(aa, s0a, r0p[i]);
                    r0p[i] = ffma2(ab, s0b, r0p[i]);
                    r1p[i] = ffma2(aa, s1a, r1p[i]);
                    r1p[i] = ffma2(ab, s1b, r1p[i]);
                }
            }
#pragma unroll
            for (int i = 0; i < 4; i++) { r0[i] = hsum2(r0p[i]); r1[i] = hsum2(r1p[i]); }
        }

        // ---- LSTM cell: f32x2 over e, two gate-halves (caps live regs) ----
        {
            float zf_[4][8];
#pragma unroll
            for (int qh = 0; qh < 2; qh++) {
                u64t z2[4][4];
#pragma unroll
                for (int i = 0; i < 4; i++) {
                    int grow = trow0 + w * 4 + i;
#pragma unroll
                    for (int k = 0; k < 4; k++)
                        z2[i][k] = pack2(g_pre_x[grow * 256 + L + 32 * (qh * 4 + k)], 0.0f);
                }
                for (int e = 0; e < 64; e += 4) {
                    ulonglong2 a2[4];
#pragma unroll
                    for (int i = 0; i < 4; i++)
                        a2[i] = *(const ulonglong2*)&H[(w * 4 + i) * 64 + e];
#pragma unroll
                    for (int k = 0; k < 4; k++) {
                        ulonglong2 w2 = *(const ulonglong2*)&WH[(L + 32 * (qh * 4 + k)) * SP + e];
#pragma unroll
                        for (int i = 0; i < 4; i++) {
                            z2[i][k] = ffma2(a2[i].x, w2.x, z2[i][k]);
                            z2[i][k] = ffma2(a2[i].y, w2.y, z2[i][k]);
                        }
                    }
                }
#pragma unroll
                for (int i = 0; i < 4; i++)
#pragma unroll
                    for (int k = 0; k < 4; k++)
                        zf_[i][qh * 4 + k] = hsum2(z2[i][k]);
            }
            __syncwarp();
#pragma unroll
            for (int i = 0; i < 4; i++) {
                int tl = w * 4 + i;
                float cc = sigf(zf_[i][2]) * c0[i] + sigf(zf_[i][0]) * tanhfast(zf_[i][4]);
                c0[i] = cc;
                float h0 = sigf(zf_[i][6]) * tanhfast(cc) + x0[i];
                float cc1 = sigf(zf_[i][3]) * c1[i] + sigf(zf_[i][1]) * tanhfast(zf_[i][5]);
                c1[i] = cc1;
                float h1 = sigf(zf_[i][7]) * tanhfast(cc1) + x1[i];
                H[tl * 64 + L] = h0;
                H[tl * 64 + 32 + L] = h1;
            }
            __syncwarp();
        }
    }

    // ---- final cosine-similarity softmax ----
    __syncthreads();
    for (int n = tid; n < NKV; n += 512) {
        float ss = 0.0f;
        for (int e = 0; e < 64; e += 4) {
            float4 v = *(const float4*)&S[n * SP + e];
            ss = fmaf(v.x, v.x, ss); ss = fmaf(v.y, v.y, ss);
            ss = fmaf(v.z, v.z, ss); ss = fmaf(v.w, v.w, ss);
        }
        SN[n] = sqrtf(ss);
    }
    __syncthreads();

    float sc[4][7];
#pragma unroll
    for (int i = 0; i < 4; i++)
#pragma unroll
        for (int q = 0; q < 7; q++) sc[i][q] = 0.0f;
    for (int e = 0; e < 64; e += 4) {
        float4 a4[4];
#pragma unroll
        for (int i = 0; i < 4; i++)
            a4[i] = *(const float4*)&H[(w * 4 + i) * 64 + e];
#pragma unroll
        for (int q = 0; q < 6; q++) {
            float4 s4 = *(const float4*)&S[(L + 32 * q) * SP + e];
#pragma unroll
            for (int i = 0; i < 4; i++) {
                sc[i][q] = fmaf(a4[i].x, s4.x, sc[i][q]);
                sc[i][q] = fmaf(a4[i].y, s4.y, sc[i][q]);
                sc[i][q] = fmaf(a4[i].z, s4.z, sc[i][q]);
                sc[i][q] = fmaf(a4[i].w, s4.w, sc[i][q]);
            }
        }
        float4 s6 = *(const float4*)&S[n6 * SP + e];
#pragma unroll
        for (int i = 0; i < 4; i++) {
            sc[i][6] = fmaf(a4[i].x, s6.x, sc[i][6]);
            sc[i][6] = fmaf(a4[i].y, s6.y, sc[i][6]);
            sc[i][6] = fmaf(a4[i].z, s6.z, sc[i][6]);
            sc[i][6] = fmaf(a4[i].w, s6.w, sc[i][6]);
        }
    }

#pragma unroll
    for (int i = 0; i < 4; i++) {
        int tl = w * 4 + i;
        float h0v = H[tl * 64 + L], h1v = H[tl * 64 + 32 + L];
        float p = h0v * h0v + h1v * h1v;
#pragma unroll
        for (int o = 16; o > 0; o >>= 1)
            p += __shfl_xor_sync(0xFFFFFFFFu, p, o);
        float tn = sqrtf(p);

#pragma unroll
        for (int q = 0; q < 6; q++) {
            float d = fmaxf(tn * SN[L + 32 * q], 1e-8f);
            sc[i][q] = sc[i][q] / d;
        }
        {
            float d6 = fmaxf(tn * SN[n6], 1e-8f);
            sc[i][6] = sc[i][6] / d6;
        }

        float m = sc[i][0];
#pragma unroll
        for (int q = 1; q < 6; q++) m = fmaxf(m, sc[i][q]);
        float v6 = (L < 8) ? sc[i][6] : -1e30f;
        m = fmaxf(m, v6);
#pragma unroll
        for (int o = 16; o > 0; o >>= 1)
            m = fmaxf(m, __shfl_xor_sync(0xFFFFFFFFu, m, o));
        float ex[7], ssum = 0.0f;
#pragma unroll
        for (int q = 0; q < 6; q++) { ex[q] = __expf(sc[i][q] - m); ssum += ex[q]; }
        ex[6] = (L < 8) ? __expf(sc[i][6] - m) : 0.0f;
        ssum += ex[6];
#pragma unroll
        for (int o = 16; o > 0; o >>= 1)
            ssum += __shfl_xor_sync(0xFFFFFFFFu, ssum, o);
        float inv = 1.0f / ssum;

        float* orow = out + (size_t)(trow0 + tl) * 200;
#pragma unroll
        for (int q = 0; q < 6; q++) orow[L + 32 * q] = ex[q] * inv;
        if (L < 8) orow[192 + L] = ex[6] * inv;
    }
}

// ---------------------------------------------------------------------------
extern "C" void kernel_launch(void* const* d_in, const int* in_sizes, int n_in,
                              void* d_out, int out_size)
{
    const int*   sup_tok = (const int*)d_in[0];
    const int*   tgt_tok = (const int*)d_in[1];
    const float* emb     = (const float*)d_in[2];
    const float* f_Wih   = (const float*)d_in[3];
    const float* f_Whh   = (const float*)d_in[4];
    const float* f_bih   = (const float*)d_in[5];
    const float* f_bhh   = (const float*)d_in[6];
    const float* gf_Wih  = (const float*)d_in[7];
    const float* gf_Whh  = (const float*)d_in[8];
    const float* gf_bih  = (const float*)d_in[9];
    const float* gf_bhh  = (const float*)d_in[10];
    const float* gb_Wih  = (const float*)d_in[11];
    const float* gb_Whh  = (const float*)d_in[12];
    const float* gb_bih  = (const float*)d_in[13];
    const float* gb_bhh  = (const float*)d_in[14];
    float* out = (float*)d_out;

    float *d_sup_enc, *d_tgt_enc, *d_pre_gf, *d_pre_gb, *d_pre_x;
    cudaGetSymbolAddress((void**)&d_sup_enc, g_sup_enc);
    cudaGetSymbolAddress((void**)&d_tgt_enc, g_tgt_enc);
    cudaGetSymbolAddress((void**)&d_pre_gf, g_pre_gf);
    cudaGetSymbolAddress((void**)&d_pre_gb, g_pre_gb);
    cudaGetSymbolAddress((void**)&d_pre_x, g_pre_x);

    // 1. embedding sums
    embed_sum_kernel<<<(SUPROWS + TGTROWS) / 16, 256>>>(sup_tok, tgt_tok, emb);

    // 2. all three gate-preactivation GEMMs in one launch
    gemm_all_kernel<<<528, 256>>>(d_sup_enc, d_tgt_enc,
                                  gf_Wih, gf_bih, gf_bhh,
                                  gb_Wih, gb_bih, gb_bhh,
                                  f_Wih, f_bih, f_bhh,
                                  d_pre_gf, d_pre_gb, d_pre_x);

    // 3. bidirectional LSTM
    lstm_kernel<<<BV * 2, 256>>>(gf_Whh, gb_Whh);

    // 4. fused attention loop + final output
    const int smem_bytes = (200 * SP + 256 * SP + 64 * 64 + 64 * AP + 200) * 4;
    cudaFuncSetAttribute(attn_kernel, cudaFuncAttributeMaxDynamicSharedMemorySize,
                         smem_bytes);
    attn_kernel<<<BV * 2, 512, smem_bytes>>>(f_Whh, out);
}

// round 13
// speedup vs baseline: 1.6804x; 1.6804x over previous
#include <cuda_runtime.h>
#include <math.h>

// Problem constants
#define BV 64
#define TV 128
#define LV 40
#define EV 64
#define NKV 200          // N*k
#define G4 256           // 4*E
#define SUPROWS (BV*NKV) // 12800
#define TGTROWS (BV*TV)  // 8192
#define KITERS 5
#define SP 68            // padded row stride for S / WH (16B aligned, conflict-free)

// Scratch (device globals; no allocation allowed)
__device__ float g_sup_enc[SUPROWS*EV];
__device__ float g_tgt_enc[TGTROWS*EV];
__device__ float g_pre_gf[SUPROWS*G4];
__device__ float g_pre_gb[SUPROWS*G4];
__device__ float g_hf[SUPROWS*EV];
__device__ float g_hb[SUPROWS*EV];
__device__ float g_pre_x[TGTROWS*G4];

__device__ __forceinline__ float sigf(float x) { return 1.0f / (1.0f + __expf(-x)); }
__device__ __forceinline__ float tanhfast(float x) {
    float a = fabsf(x);
    float t = __expf(-2.0f * a);
    float r = (1.0f - t) / (1.0f + t);
    return copysignf(r, x);
}

// ---------------------------------------------------------------------------
// Kernel 1: embedding gather-sums. 16 threads per row (float4 per thread).
// ---------------------------------------------------------------------------
__global__ __launch_bounds__(256) void embed_sum_kernel(
    const int* __restrict__ sup_tok,
    const int* __restrict__ tgt_tok,
    const float* __restrict__ emb)
{
    int row = blockIdx.x * 16 + (threadIdx.x >> 4);
    int e = (threadIdx.x & 15) * 4;
    const int* tok;
    float* out;
    if (row < SUPROWS) {
        tok = sup_tok + row * LV;
        out = g_sup_enc + row * EV;
    } else {
        int r2 = row - SUPROWS;
        tok = tgt_tok + r2 * LV;
        out = g_tgt_enc + r2 * EV;
    }
    float ax = 0.f, ay = 0.f, az = 0.f, aw = 0.f;
#pragma unroll 8
    for (int l = 0; l < LV; l++) {
        int t = tok[l];
        float4 v = *(const float4*)&emb[t * EV + e];
        ax += v.x; ay += v.y; az += v.z; aw += v.w;
    }
    float4 o; o.x = ax; o.y = ay; o.z = az; o.w = aw;
    *(float4*)&out[e] = o;
}

// ---------------------------------------------------------------------------
// Kernel 2: gf + gb gate-preactivation GEMMs (400 blocks).
// C[M,256] = A[M,64] @ W[256,64]^T + (b1+b2). W row-major [256][65].
// ---------------------------------------------------------------------------
__global__ __launch_bounds__(256, 2) void gemm_gfgb_kernel(
    const float* __restrict__ sup_enc_g,
    const float* __restrict__ gf_W, const float* __restrict__ gf_b1, const float* __restrict__ gf_b2,
    const float* __restrict__ gb_W, const float* __restrict__ gb_b1, const float* __restrict__ gb_b2,
    float* __restrict__ pre_gf, float* __restrict__ pre_gb)
{
    __shared__ float A_sh[64][64];
    __shared__ float W_sh[256][65];
    __shared__ float bias_sh[256];

    int blk = blockIdx.x;
    const float *A = sup_enc_g, *W, *b1, *b2;
    float* C;
    int row0;
    if (blk < 200) { W = gf_W; b1 = gf_b1; b2 = gf_b2; C = pre_gf; row0 = blk * 64; }
    else           { W = gb_W; b1 = gb_b1; b2 = gb_b2; C = pre_gb; row0 = (blk - 200) * 64; }

    int tid = threadIdx.x;
    int tx = tid & 31, ty = tid >> 5;

    for (int idx = tid; idx < 256 * 64; idx += 256) {
        int j = idx >> 6, e = idx & 63;
        W_sh[j][e] = W[idx];
    }
    bias_sh[tid] = b1[tid] + b2[tid];
    for (int idx = tid; idx < 64 * 64; idx += 256) {
        A_sh[idx >> 6][idx & 63] = A[row0 * 64 + idx];
    }
    __syncthreads();

    float acc[8][8];
#pragma unroll
    for (int i = 0; i < 8; i++)
#pragma unroll
        for (int q = 0; q < 8; q++) acc[i][q] = 0.0f;

#pragma unroll 4
    for (int e = 0; e < 64; e++) {
        float a[8], bb[8];
#pragma unroll
        for (int i = 0; i < 8; i++) a[i] = A_sh[ty * 8 + i][e];
#pragma unroll
        for (int q = 0; q < 8; q++) bb[q] = W_sh[tx + 32 * q][e];
#pragma unroll
        for (int i = 0; i < 8; i++)
#pragma unroll
            for (int q = 0; q < 8; q++) acc[i][q] = fmaf(a[i], bb[q], acc[i][q]);
    }

#pragma unroll
    for (int i = 0; i < 8; i++) {
        int r = row0 + ty * 8 + i;
#pragma unroll
        for (int q = 0; q < 8; q++) {
            int j = tx + 32 * q;
            C[r * 256 + j] = acc[i][q] + bias_sh[j];
        }
    }
}

// ---------------------------------------------------------------------------
// Kernel 3 (merged): blocks 0..127 = bidirectional LSTM chains;
// blocks 128..255 = f-GEMM (pre_x). The f-GEMM fills the issue slots the
// latency-bound LSTM leaves idle (2 blocks/SM, one wave, no extra launch).
// ---------------------------------------------------------------------------
__global__ __launch_bounds__(256, 2) void lstm_gemmf_kernel(
    const float* __restrict__ gf_Whh, const float* __restrict__ gb_Whh,
    const float* __restrict__ tgt_enc_g,
    const float* __restrict__ f_W, const float* __restrict__ f_b1,
    const float* __restrict__ f_b2,
    float* __restrict__ pre_x)
{
    __shared__ __align__(16) float A_sh[64][64];
    __shared__ float W_sh[256][65];
    __shared__ float bias_sh[256];

    int tid = threadIdx.x;

    if (blockIdx.x < 128) {
        // ---------------- LSTM branch ----------------
        int bx = blockIdx.x;
        int dir = bx & 1, b = bx >> 1;
        int L = tid & 31, w = tid >> 5;
        int ep = w * 8 + (L & 7);
        int gate = L >> 3;
        int j = gate * 64 + ep;

        const float* Whh = dir ? gb_Whh : gf_Whh;
        const float* pre = dir ? g_pre_gb : g_pre_gf;
        float* out = dir ? g_hb : g_hf;

        float wr[64];
#pragma unroll
        for (int e = 0; e < 64; e++) wr[e] = Whh[j * 64 + e];

        float (*h_sh)[64] = reinterpret_cast<float(*)[64]>(&A_sh[0][0]);
        if (tid < 64) h_sh[0][tid] = 0.0f;
        float c = 0.0f;
        __syncthreads();

        int srow_first = dir ? (NKV - 1) : 0;
        float z_next = pre[(b * NKV + srow_first) * 256 + j];

        int cur = 0;
        for (int s = 0; s < NKV; s++) {
            int srow = dir ? (NKV - 1 - s) : s;
            int row = b * NKV + srow;
            float z = z_next;
            if (s + 1 < NKV) {
                int nr = dir ? (NKV - 2 - s) : (s + 1);
                z_next = pre[(b * NKV + nr) * 256 + j];
            }

            const float4* h4 = (const float4*)h_sh[cur];
            float a0 = 0.f, a1 = 0.f, a2 = 0.f, a3 = 0.f;
            float b0 = 0.f, b1v = 0.f, b2v = 0.f, b3 = 0.f;
#pragma unroll
            for (int q = 0; q < 16; q += 2) {
                float4 hv0 = h4[q];
                float4 hv1 = h4[q + 1];
                a0  = fmaf(hv0.x, wr[4 * q + 0], a0);
                a1  = fmaf(hv0.y, wr[4 * q + 1], a1);
                a2  = fmaf(hv0.z, wr[4 * q + 2], a2);
                a3  = fmaf(hv0.w, wr[4 * q + 3], a3);
                b0  = fmaf(hv1.x, wr[4 * q + 4], b0);
                b1v = fmaf(hv1.y, wr[4 * q + 5], b1v);
                b2v = fmaf(hv1.z, wr[4 * q + 6], b2v);
                b3  = fmaf(hv1.w, wr[4 * q + 7], b3);
            }
            z += ((a0 + a1) + (a2 + a3)) + ((b0 + b1v) + (b2v + b3));

            float zf = __shfl_down_sync(0xFFFFFFFFu, z, 8);
            float zg = __shfl_down_sync(0xFFFFFFFFu, z, 16);
            float zo = __shfl_down_sync(0xFFFFFFFFu, z, 24);
            if (L < 8) {
                c = sigf(zf) * c + sigf(z) * tanhfast(zg);
                float h = sigf(zo) * tanhfast(c);
                h_sh[cur ^ 1][ep] = h;
                out[row * 64 + ep] = h;
            }
            cur ^= 1;
            __syncthreads();
        }
    } else {
        // ---------------- f-GEMM branch (pre_x) ----------------
        int blk = blockIdx.x - 128;
        int row0 = blk * 64;
        int tx = tid & 31, ty = tid >> 5;

        for (int idx = tid; idx < 256 * 64; idx += 256) {
            int j = idx >> 6, e = idx & 63;
            W_sh[j][e] = f_W[idx];
        }
        bias_sh[tid] = f_b1[tid] + f_b2[tid];
        for (int idx = tid; idx < 64 * 64; idx += 256) {
            A_sh[idx >> 6][idx & 63] = tgt_enc_g[row0 * 64 + idx];
        }
        __syncthreads();

        float acc[8][8];
#pragma unroll
        for (int i = 0; i < 8; i++)
#pragma unroll
            for (int q = 0; q < 8; q++) acc[i][q] = 0.0f;

#pragma unroll 4
        for (int e = 0; e < 64; e++) {
            float a[8], bb[8];
#pragma unroll
            for (int i = 0; i < 8; i++) a[i] = A_sh[ty * 8 + i][e];
#pragma unroll
            for (int q = 0; q < 8; q++) bb[q] = W_sh[tx + 32 * q][e];
#pragma unroll
            for (int i = 0; i < 8; i++)
#pragma unroll
                for (int q = 0; q < 8; q++) acc[i][q] = fmaf(a[i], bb[q], acc[i][q]);
        }

#pragma unroll
        for (int i = 0; i < 8; i++) {
            int r = row0 + ty * 8 + i;
#pragma unroll
            for (int q = 0; q < 8; q++) {
                int j = tx + 32 * q;
                pre_x[r * 256 + j] = acc[i][q] + bias_sh[j];
            }
        }
    }
}

// ---------------------------------------------------------------------------
// Kernel 4: fused K-hop attention + final cosine softmax (the proven R8 307µs
// version, fully scalar). 512 threads, 16 warps x 4 target rows,
// __syncwarp-only inner flow. Cell e-loop fused: WH streamed once per iter.
// ---------------------------------------------------------------------------
__global__ __launch_bounds__(512) void attn_kernel(
    const float* __restrict__ f_Whh, float* __restrict__ out)
{
    extern __shared__ float sm[];
    float* S   = sm;                      // [200][SP]
    float* WH  = S + 200 * SP;            // [256][SP]
    float* H   = WH + 256 * SP;           // [64][64]
    float* ATT = H + 64 * 64;             // [64][200]
    float* SN  = ATT + 64 * 200;          // [200]

    int tid = threadIdx.x;
    int L = tid & 31, w = tid >> 5;       // w = 0..15
    int b = blockIdx.x >> 1, half = blockIdx.x & 1;
    int srow0 = b * NKV;
    int trow0 = b * TV + half * 64;

    for (int idx = tid; idx < NKV * 64; idx += 512) {
        int n = idx >> 6, e = idx & 63;
        int gr = (srow0 + n) * 64 + e;
        S[n * SP + e] = g_hf[gr] + g_hb[gr] + g_sup_enc[gr];
    }
    for (int idx = tid; idx < 256 * 64; idx += 512) {
        int j = idx >> 6, e = idx & 63;
        WH[j * SP + e] = f_Whh[idx];
    }
    for (int idx = tid; idx < 64 * 64; idx += 512) H[idx] = 0.0f;

    float x0[4], x1[4], r0[4], r1[4], c0[4], c1[4];
#pragma unroll
    for (int i = 0; i < 4; i++) {
        int grow = trow0 + w * 4 + i;
        x0[i] = g_tgt_enc[grow * 64 + L];
        x1[i] = g_tgt_enc[grow * 64 + 32 + L];
        r0[i] = r1[i] = c0[i] = c1[i] = 0.0f;
    }
    __syncthreads();

    int n6 = 192 + (L & 7);

    for (int iter = 0; iter < KITERS; iter++) {
        // h = h + r
#pragma unroll
        for (int i = 0; i < 4; i++) {
            int tl = w * 4 + i;
            H[tl * 64 + L]      += r0[i];
            H[tl * 64 + 32 + L] += r1[i];
        }
        __syncwarp();

        if (iter < KITERS - 1) {
            float sc[4][7];
#pragma unroll
            for (int i = 0; i < 4; i++)
#pragma unroll
                for (int q = 0; q < 7; q++) sc[i][q] = 0.0f;

            for (int e = 0; e < 64; e += 4) {
                float4 a4[4];
#pragma unroll
                for (int i = 0; i < 4; i++)
                    a4[i] = *(const float4*)&H[(w * 4 + i) * 64 + e];
#pragma unroll
                for (int q = 0; q < 6; q++) {
                    float4 s4 = *(const float4*)&S[(L + 32 * q) * SP + e];
#pragma unroll
                    for (int i = 0; i < 4; i++) {
                        sc[i][q] = fmaf(a4[i].x, s4.x, sc[i][q]);
                        sc[i][q] = fmaf(a4[i].y, s4.y, sc[i][q]);
                        sc[i][q] = fmaf(a4[i].z, s4.z, sc[i][q]);
                        sc[i][q] = fmaf(a4[i].w, s4.w, sc[i][q]);
                    }
                }
                float4 s6 = *(const float4*)&S[n6 * SP + e];
#pragma unroll
                for (int i = 0; i < 4; i++) {
                    sc[i][6] = fmaf(a4[i].x, s6.x, sc[i][6]);
                    sc[i][6] = fmaf(a4[i].y, s6.y, sc[i][6]);
                    sc[i][6] = fmaf(a4[i].z, s6.z, sc[i][6]);
                    sc[i][6] = fmaf(a4[i].w, s6.w, sc[i][6]);
                }
            }

            // softmax over 200, write att to SMEM
#pragma unroll
            for (int i = 0; i < 4; i++) {
                float m = sc[i][0];
#pragma unroll
                for (int q = 1; q < 6; q++) m = fmaxf(m, sc[i][q]);
                float v6 = (L < 8) ? sc[i][6] : -1e30f;
                m = fmaxf(m, v6);
#pragma unroll
                for (int o = 16; o > 0; o >>= 1)
                    m = fmaxf(m, __shfl_xor_sync(0xFFFFFFFFu, m, o));
                float ex[7], ssum = 0.0f;
#pragma unroll
                for (int q = 0; q < 6; q++) { ex[q] = __expf(sc[i][q] - m); ssum += ex[q]; }
                ex[6] = (L < 8) ? __expf(sc[i][6] - m) : 0.0f;
                ssum += ex[6];
#pragma unroll
                for (int o = 16; o > 0; o >>= 1)
                    ssum += __shfl_xor_sync(0xFFFFFFFFu, ssum, o);
                float inv = 1.0f / ssum;
                int tl = w * 4 + i;
#pragma unroll
                for (int q = 0; q < 6; q++) ATT[tl * 200 + L + 32 * q] = ex[q] * inv;
                if (L < 8) ATT[tl * 200 + 192 + L] = ex[6] * inv;
            }
            __syncwarp();

            // r[t][e] = sum_n att[t][n] * S[n][e]
#pragma unroll
            for (int i = 0; i < 4; i++) { r0[i] = 0.0f; r1[i] = 0.0f; }
            for (int n = 0; n < NKV; n += 4) {
                float s0a = S[(n + 0) * SP + L],      s1a = S[(n + 0) * SP + 32 + L];
                float s0b = S[(n + 1) * SP + L],      s1b = S[(n + 1) * SP + 32 + L];
                float s0c = S[(n + 2) * SP + L],      s1c = S[(n + 2) * SP + 32 + L];
                float s0d = S[(n + 3) * SP + L],      s1d = S[(n + 3) * SP + 32 + L];
#pragma unroll
                for (int i = 0; i < 4; i++) {
                    float4 a = *(const float4*)&ATT[(w * 4 + i) * 200 + n];
                    r0[i] = fmaf(a.x, s0a, r0[i]); r1[i] = fmaf(a.x, s1a, r1[i]);
                    r0[i] = fmaf(a.y, s0b, r0[i]); r1[i] = fmaf(a.y, s1b, r1[i]);
                    r0[i] = fmaf(a.z, s0c, r0[i]); r1[i] = fmaf(a.z, s1c, r1[i]);
                    r0[i] = fmaf(a.w, s0d, r0[i]); r1[i] = fmaf(a.w, s1d, r1[i]);
                }
            }
        }

        // LSTM cell: fused single e-loop, WH streamed once per warp.
        {
            float z[4][8];
#pragma unroll
            for (int i = 0; i < 4; i++) {
                int grow = trow0 + w * 4 + i;
#pragma unroll
                for (int q = 0; q < 8; q++)
                    z[i][q] = g_pre_x[grow * 256 + L + 32 * q];
            }
            for (int e = 0; e < 64; e += 4) {
                float4 a4[4];
#pragma unroll
                for (int i = 0; i < 4; i++)
                    a4[i] = *(const float4*)&H[(w * 4 + i) * 64 + e];
#pragma unroll
                for (int q = 0; q < 8; q++) {
                    float4 w4 = *(const float4*)&WH[(L + 32 * q) * SP + e];
#pragma unroll
                    for (int i = 0; i < 4; i++) {
                        z[i][q] = fmaf(a4[i].x, w4.x, z[i][q]);
                        z[i][q] = fmaf(a4[i].y, w4.y, z[i][q]);
                        z[i][q] = fmaf(a4[i].z, w4.z, z[i][q]);
                        z[i][q] = fmaf(a4[i].w, w4.w, z[i][q]);
                    }
                }
            }
            __syncwarp();
#pragma unroll
            for (int i = 0; i < 4; i++) {
                int tl = w * 4 + i;
                float cc = sigf(z[i][2]) * c0[i] + sigf(z[i][0]) * tanhfast(z[i][4]);
                c0[i] = cc;
                float h0 = sigf(z[i][6]) * tanhfast(cc) + x0[i];
                float cc1 = sigf(z[i][3]) * c1[i] + sigf(z[i][1]) * tanhfast(z[i][5]);
                c1[i] = cc1;
                float h1 = sigf(z[i][7]) * tanhfast(cc1) + x1[i];
                H[tl * 64 + L] = h0;
                H[tl * 64 + 32 + L] = h1;
            }
            __syncwarp();
        }
    }

    // ---- final cosine-similarity softmax ----
    __syncthreads();
    for (int n = tid; n < NKV; n += 512) {
        float ss = 0.0f;
        for (int e = 0; e < 64; e += 4) {
            float4 v = *(const float4*)&S[n * SP + e];
            ss = fmaf(v.x, v.x, ss); ss = fmaf(v.y, v.y, ss);
            ss = fmaf(v.z, v.z, ss); ss = fmaf(v.w, v.w, ss);
        }
        SN[n] = sqrtf(ss);
    }
    __syncthreads();

    float sc[4][7];
#pragma unroll
    for (int i = 0; i < 4; i++)
#pragma unroll
        for (int q = 0; q < 7; q++) sc[i][q] = 0.0f;
    for (int e = 0; e < 64; e += 4) {
        float4 a4[4];
#pragma unroll
        for (int i = 0; i < 4; i++)
            a4[i] = *(const float4*)&H[(w * 4 + i) * 64 + e];
#pragma unroll
        for (int q = 0; q < 6; q++) {
            float4 s4 = *(const float4*)&S[(L + 32 * q) * SP + e];
#pragma unroll
            for (int i = 0; i < 4; i++) {
                sc[i][q] = fmaf(a4[i].x, s4.x, sc[i][q]);
                sc[i][q] = fmaf(a4[i].y, s4.y, sc[i][q]);
                sc[i][q] = fmaf(a4[i].z, s4.z, sc[i][q]);
                sc[i][q] = fmaf(a4[i].w, s4.w, sc[i][q]);
            }
        }
        float4 s6 = *(const float4*)&S[n6 * SP + e];
#pragma unroll
        for (int i = 0; i < 4; i++) {
            sc[i][6] = fmaf(a4[i].x, s6.x, sc[i][6]);
            sc[i][6] = fmaf(a4[i].y, s6.y, sc[i][6]);
            sc[i][6] = fmaf(a4[i].z, s6.z, sc[i][6]);
            sc[i][6] = fmaf(a4[i].w, s6.w, sc[i][6]);
        }
    }

#pragma unroll
    for (int i = 0; i < 4; i++) {
        int tl = w * 4 + i;
        float h0v = H[tl * 64 + L], h1v = H[tl * 64 + 32 + L];
        float p = h0v * h0v + h1v * h1v;
#pragma unroll
        for (int o = 16; o > 0; o >>= 1)
            p += __shfl_xor_sync(0xFFFFFFFFu, p, o);
        float tn = sqrtf(p);

#pragma unroll
        for (int q = 0; q < 6; q++) {
            float d = fmaxf(tn * SN[L + 32 * q], 1e-8f);
            sc[i][q] = __fdividef(sc[i][q], d);
        }
        {
            float d6 = fmaxf(tn * SN[n6], 1e-8f);
            sc[i][6] = __fdividef(sc[i][6], d6);
        }

        float m = sc[i][0];
#pragma unroll
        for (int q = 1; q < 6; q++) m = fmaxf(m, sc[i][q]);
        float v6 = (L < 8) ? sc[i][6] : -1e30f;
        m = fmaxf(m, v6);
#pragma unroll
        for (int o = 16; o > 0; o >>= 1)
            m = fmaxf(m, __shfl_xor_sync(0xFFFFFFFFu, m, o));
        float ex[7], ssum = 0.0f;
#pragma unroll
        for (int q = 0; q < 6; q++) { ex[q] = __expf(sc[i][q] - m); ssum += ex[q]; }
        ex[6] = (L < 8) ? __expf(sc[i][6] - m) : 0.0f;
        ssum += ex[6];
#pragma unroll
        for (int o = 16; o > 0; o >>= 1)
            ssum += __shfl_xor_sync(0xFFFFFFFFu, ssum, o);
        float inv = 1.0f / ssum;

        float* orow = out + (size_t)(trow0 + tl) * 200;
#pragma unroll
        for (int q = 0; q < 6; q++) orow[L + 32 * q] = ex[q] * inv;
        if (L < 8) orow[192 + L] = ex[6] * inv;
    }
}

// ---------------------------------------------------------------------------
extern "C" void kernel_launch(void* const* d_in, const int* in_sizes, int n_in,
                              void* d_out, int out_size)
{
    const int*   sup_tok = (const int*)d_in[0];
    const int*   tgt_tok = (const int*)d_in[1];
    const float* emb     = (const float*)d_in[2];
    const float* f_Wih   = (const float*)d_in[3];
    const float* f_Whh   = (const float*)d_in[4];
    const float* f_bih   = (const float*)d_in[5];
    const float* f_bhh   = (const float*)d_in[6];
    const float* gf_Wih  = (const float*)d_in[7];
    const float* gf_Whh  = (const float*)d_in[8];
    const float* gf_bih  = (const float*)d_in[9];
    const float* gf_bhh  = (const float*)d_in[10];
    const float* gb_Wih  = (const float*)d_in[11];
    const float* gb_Whh  = (const float*)d_in[12];
    const float* gb_bih  = (const float*)d_in[13];
    const float* gb_bhh  = (const float*)d_in[14];
    float* out = (float*)d_out;

    float *d_sup_enc, *d_tgt_enc, *d_pre_gf, *d_pre_gb, *d_pre_x;
    cudaGetSymbolAddress((void**)&d_sup_enc, g_sup_enc);
    cudaGetSymbolAddress((void**)&d_tgt_enc, g_tgt_enc);
    cudaGetSymbolAddress((void**)&d_pre_gf, g_pre_gf);
    cudaGetSymbolAddress((void**)&d_pre_gb, g_pre_gb);
    cudaGetSymbolAddress((void**)&d_pre_x, g_pre_x);

    // 1. embedding sums (support + target)
    embed_sum_kernel<<<(SUPROWS + TGTROWS) / 16, 256>>>(sup_tok, tgt_tok, emb);

    // 2. gf + gb gate-preactivation GEMMs (lstm's inputs)
    gemm_gfgb_kernel<<<400, 256>>>(d_sup_enc,
                                   gf_Wih, gf_bih, gf_bhh,
                                   gb_Wih, gb_bih, gb_bhh,
                                   d_pre_gf, d_pre_gb);

    // 3. merged: LSTM chains (blocks 0-127) + f-GEMM pre_x (blocks 128-255).
    //    The f-GEMM hides entirely in the LSTM's idle issue slots.
    lstm_gemmf_kernel<<<256, 256>>>(gf_Whh, gb_Whh,
                                    d_tgt_enc, f_Wih, f_bih, f_bhh,
                                    d_pre_x);

    // 4. fused attention loop + final output
    const int smem_bytes = (200 * SP + 256 * SP + 64 * 64 + 64 * 200 + 200) * 4;
    cudaFuncSetAttribute(attn_kernel, cudaFuncAttributeMaxDynamicSharedMemorySize,
                         smem_bytes);
    attn_kernel<<<BV * 2, 512, smem_bytes>>>(f_Whh, out);
}

// round 14
// speedup vs baseline: 1.7308x; 1.0300x over previous
#include <cuda_runtime.h>
#include <math.h>

// Problem constants
#define BV 64
#define TV 128
#define LV 40
#define EV 64
#define NKV 200          // N*k
#define G4 256           // 4*E
#define SUPROWS (BV*NKV) // 12800
#define TGTROWS (BV*TV)  // 8192
#define KITERS 5
#define SP 68            // padded row stride for S / WH (16B aligned, conflict-free)

// Scratch (device globals; no allocation allowed)
__device__ float g_sup_enc[SUPROWS*EV];
__device__ float g_tgt_enc[TGTROWS*EV];
__device__ float g_pre_gf[SUPROWS*G4];
__device__ float g_pre_gb[SUPROWS*G4];
__device__ float g_hf[SUPROWS*EV];
__device__ float g_hb[SUPROWS*EV];
__device__ float g_pre_x[TGTROWS*G4];

typedef unsigned long long u64t;

__device__ __forceinline__ u64t ffma2(u64t a, u64t b, u64t c) {
    u64t d;
    asm("fma.rn.f32x2 %0,%1,%2,%3;" : "=l"(d) : "l"(a), "l"(b), "l"(c));
    return d;
}
__device__ __forceinline__ float hsum2(u64t v) {
    float lo, hi;
    asm("mov.b64 {%0,%1},%2;" : "=f"(lo), "=f"(hi) : "l"(v));
    return lo + hi;
}

__device__ __forceinline__ float sigf(float x) { return 1.0f / (1.0f + __expf(-x)); }
__device__ __forceinline__ float tanhfast(float x) {
    float a = fabsf(x);
    float t = __expf(-2.0f * a);
    float r = (1.0f - t) / (1.0f + t);
    return copysignf(r, x);
}

// ---------------------------------------------------------------------------
// Kernel 1: embedding gather-sums. 16 threads per row (float4 per thread).
// ---------------------------------------------------------------------------
__global__ __launch_bounds__(256) void embed_sum_kernel(
    const int* __restrict__ sup_tok,
    const int* __restrict__ tgt_tok,
    const float* __restrict__ emb)
{
    int row = blockIdx.x * 16 + (threadIdx.x >> 4);
    int e = (threadIdx.x & 15) * 4;
    const int* tok;
    float* out;
    if (row < SUPROWS) {
        tok = sup_tok + row * LV;
        out = g_sup_enc + row * EV;
    } else {
        int r2 = row - SUPROWS;
        tok = tgt_tok + r2 * LV;
        out = g_tgt_enc + r2 * EV;
    }
    float ax = 0.f, ay = 0.f, az = 0.f, aw = 0.f;
#pragma unroll 8
    for (int l = 0; l < LV; l++) {
        int t = tok[l];
        float4 v = *(const float4*)&emb[t * EV + e];
        ax += v.x; ay += v.y; az += v.z; aw += v.w;
    }
    float4 o; o.x = ax; o.y = ay; o.z = az; o.w = aw;
    *(float4*)&out[e] = o;
}

// ---------------------------------------------------------------------------
// Kernel 2: gf + gb gate-preactivation GEMMs (400 blocks).
// C[M,256] = A[M,64] @ W[256,64]^T + (b1+b2). W row-major [256][65].
// ---------------------------------------------------------------------------
__global__ __launch_bounds__(256, 2) void gemm_gfgb_kernel(
    const float* __restrict__ sup_enc_g,
    const float* __restrict__ gf_W, const float* __restrict__ gf_b1, const float* __restrict__ gf_b2,
    const float* __restrict__ gb_W, const float* __restrict__ gb_b1, const float* __restrict__ gb_b2,
    float* __restrict__ pre_gf, float* __restrict__ pre_gb)
{
    __shared__ float A_sh[64][64];
    __shared__ float W_sh[256][65];
    __shared__ float bias_sh[256];

    int blk = blockIdx.x;
    const float *A = sup_enc_g, *W, *b1, *b2;
    float* C;
    int row0;
    if (blk < 200) { W = gf_W; b1 = gf_b1; b2 = gf_b2; C = pre_gf; row0 = blk * 64; }
    else           { W = gb_W; b1 = gb_b1; b2 = gb_b2; C = pre_gb; row0 = (blk - 200) * 64; }

    int tid = threadIdx.x;
    int tx = tid & 31, ty = tid >> 5;

    for (int idx = tid; idx < 256 * 64; idx += 256) {
        int j = idx >> 6, e = idx & 63;
        W_sh[j][e] = W[idx];
    }
    bias_sh[tid] = b1[tid] + b2[tid];
    for (int idx = tid; idx < 64 * 64; idx += 256) {
        A_sh[idx >> 6][idx & 63] = A[row0 * 64 + idx];
    }
    __syncthreads();

    float acc[8][8];
#pragma unroll
    for (int i = 0; i < 8; i++)
#pragma unroll
        for (int q = 0; q < 8; q++) acc[i][q] = 0.0f;

#pragma unroll 4
    for (int e = 0; e < 64; e++) {
        float a[8], bb[8];
#pragma unroll
        for (int i = 0; i < 8; i++) a[i] = A_sh[ty * 8 + i][e];
#pragma unroll
        for (int q = 0; q < 8; q++) bb[q] = W_sh[tx + 32 * q][e];
#pragma unroll
        for (int i = 0; i < 8; i++)
#pragma unroll
            for (int q = 0; q < 8; q++) acc[i][q] = fmaf(a[i], bb[q], acc[i][q]);
    }

#pragma unroll
    for (int i = 0; i < 8; i++) {
        int r = row0 + ty * 8 + i;
#pragma unroll
        for (int q = 0; q < 8; q++) {
            int j = tx + 32 * q;
            C[r * 256 + j] = acc[i][q] + bias_sh[j];
        }
    }
}

// ---------------------------------------------------------------------------
// Kernel 3 (merged): blocks 0..127 = bidirectional LSTM chains (f32x2 dot);
// blocks 128..255 = f-GEMM (pre_x) hiding in the LSTM's idle issue slots.
// ---------------------------------------------------------------------------
__global__ __launch_bounds__(256, 2) void lstm_gemmf_kernel(
    const float* __restrict__ gf_Whh, const float* __restrict__ gb_Whh,
    const float* __restrict__ tgt_enc_g,
    const float* __restrict__ f_W, const float* __restrict__ f_b1,
    const float* __restrict__ f_b2,
    float* __restrict__ pre_x)
{
    __shared__ __align__(16) float A_sh[64][64];
    __shared__ float W_sh[256][65];
    __shared__ float bias_sh[256];

    int tid = threadIdx.x;

    if (blockIdx.x < 128) {
        // ---------------- LSTM branch ----------------
        int bx = blockIdx.x;
        int dir = bx & 1, b = bx >> 1;
        int L = tid & 31, w = tid >> 5;
        int ep = w * 8 + (L & 7);
        int gate = L >> 3;
        int j = gate * 64 + ep;

        const float* Whh = dir ? gb_Whh : gf_Whh;
        const float* pre = dir ? g_pre_gb : g_pre_gf;
        float* out = dir ? g_hb : g_hf;

        // weight row as f32x2 pairs
        u64t wr2[32];
        {
            const ulonglong2* wv = (const ulonglong2*)&Whh[j * 64];
#pragma unroll
            for (int q = 0; q < 16; q++) {
                ulonglong2 v = wv[q];
                wr2[2 * q]     = v.x;
                wr2[2 * q + 1] = v.y;
            }
        }

        float (*h_sh)[64] = reinterpret_cast<float(*)[64]>(&A_sh[0][0]);
        if (tid < 64) h_sh[0][tid] = 0.0f;
        float c = 0.0f;
        __syncthreads();

        int srow_first = dir ? (NKV - 1) : 0;
        float z_next = pre[(b * NKV + srow_first) * 256 + j];

        int cur = 0;
        for (int s = 0; s < NKV; s++) {
            int srow = dir ? (NKV - 1 - s) : s;
            int row = b * NKV + srow;
            float z = z_next;
            if (s + 1 < NKV) {
                int nr = dir ? (NKV - 2 - s) : (s + 1);
                z_next = pre[(b * NKV + nr) * 256 + j];
            }

            const ulonglong2* hu = (const ulonglong2*)h_sh[cur];
            u64t a0 = 0ull, a1 = 0ull, a2 = 0ull, a3 = 0ull;
#pragma unroll
            for (int q = 0; q < 16; q += 2) {
                ulonglong2 h0v = hu[q];
                ulonglong2 h1v = hu[q + 1];
                a0 = ffma2(h0v.x, wr2[2 * q],     a0);
                a1 = ffma2(h0v.y, wr2[2 * q + 1], a1);
                a2 = ffma2(h1v.x, wr2[2 * q + 2], a2);
                a3 = ffma2(h1v.y, wr2[2 * q + 3], a3);
            }
            z += (hsum2(a0) + hsum2(a1)) + (hsum2(a2) + hsum2(a3));

            float zf = __shfl_down_sync(0xFFFFFFFFu, z, 8);
            float zg = __shfl_down_sync(0xFFFFFFFFu, z, 16);
            float zo = __shfl_down_sync(0xFFFFFFFFu, z, 24);
            if (L < 8) {
                c = sigf(zf) * c + sigf(z) * tanhfast(zg);
                float h = sigf(zo) * tanhfast(c);
                h_sh[cur ^ 1][ep] = h;
                out[row * 64 + ep] = h;
            }
            cur ^= 1;
            __syncthreads();
        }
    } else {
        // ---------------- f-GEMM branch (pre_x) ----------------
        int blk = blockIdx.x - 128;
        int row0 = blk * 64;
        int tx = tid & 31, ty = tid >> 5;

        for (int idx = tid; idx < 256 * 64; idx += 256) {
            int j = idx >> 6, e = idx & 63;
            W_sh[j][e] = f_W[idx];
        }
        bias_sh[tid] = f_b1[tid] + f_b2[tid];
        for (int idx = tid; idx < 64 * 64; idx += 256) {
            A_sh[idx >> 6][idx & 63] = tgt_enc_g[row0 * 64 + idx];
        }
        __syncthreads();

        float acc[8][8];
#pragma unroll
        for (int i = 0; i < 8; i++)
#pragma unroll
            for (int q = 0; q < 8; q++) acc[i][q] = 0.0f;

#pragma unroll 4
        for (int e = 0; e < 64; e++) {
            float a[8], bb[8];
#pragma unroll
            for (int i = 0; i < 8; i++) a[i] = A_sh[ty * 8 + i][e];
#pragma unroll
            for (int q = 0; q < 8; q++) bb[q] = W_sh[tx + 32 * q][e];
#pragma unroll
            for (int i = 0; i < 8; i++)
#pragma unroll
                for (int q = 0; q < 8; q++) acc[i][q] = fmaf(a[i], bb[q], acc[i][q]);
        }

#pragma unroll
        for (int i = 0; i < 8; i++) {
            int r = row0 + ty * 8 + i;
#pragma unroll
            for (int q = 0; q < 8; q++) {
                int j = tx + 32 * q;
                pre_x[r * 256 + j] = acc[i][q] + bias_sh[j];
            }
        }
    }
}

// ---------------------------------------------------------------------------
// Kernel 4: fused K-hop attention + final cosine softmax (scalar, proven).
// 512 threads, 16 warps x 4 target rows, __syncwarp-only inner flow.
// r-addition fused into the cell finish (H gets h_next + r directly;
// last iter writes plain h_next, matching the reference).
// ---------------------------------------------------------------------------
__global__ __launch_bounds__(512) void attn_kernel(
    const float* __restrict__ f_Whh, float* __restrict__ out)
{
    extern __shared__ float sm[];
    float* S   = sm;                      // [200][SP]
    float* WH  = S + 200 * SP;            // [256][SP]
    float* H   = WH + 256 * SP;           // [64][64]
    float* ATT = H + 64 * 64;             // [64][200]
    float* SN  = ATT + 64 * 200;          // [200]

    int tid = threadIdx.x;
    int L = tid & 31, w = tid >> 5;       // w = 0..15
    int b = blockIdx.x >> 1, half = blockIdx.x & 1;
    int srow0 = b * NKV;
    int trow0 = b * TV + half * 64;

    for (int idx = tid; idx < NKV * 64; idx += 512) {
        int n = idx >> 6, e = idx & 63;
        int gr = (srow0 + n) * 64 + e;
        S[n * SP + e] = g_hf[gr] + g_hb[gr] + g_sup_enc[gr];
    }
    for (int idx = tid; idx < 256 * 64; idx += 512) {
        int j = idx >> 6, e = idx & 63;
        WH[j * SP + e] = f_Whh[idx];
    }
    for (int idx = tid; idx < 64 * 64; idx += 512) H[idx] = 0.0f;

    float x0[4], x1[4], r0[4], r1[4], c0[4], c1[4];
#pragma unroll
    for (int i = 0; i < 4; i++) {
        int grow = trow0 + w * 4 + i;
        x0[i] = g_tgt_enc[grow * 64 + L];
        x1[i] = g_tgt_enc[grow * 64 + 32 + L];
        r0[i] = r1[i] = c0[i] = c1[i] = 0.0f;
    }
    __syncthreads();

    int n6 = 192 + (L & 7);

    for (int iter = 0; iter < KITERS; iter++) {
        bool not_last = (iter < KITERS - 1);

        if (not_last) {
            float sc[4][7];
#pragma unroll
            for (int i = 0; i < 4; i++)
#pragma unroll
                for (int q = 0; q < 7; q++) sc[i][q] = 0.0f;

            for (int e = 0; e < 64; e += 4) {
                float4 a4[4];
#pragma unroll
                for (int i = 0; i < 4; i++)
                    a4[i] = *(const float4*)&H[(w * 4 + i) * 64 + e];
#pragma unroll
                for (int q = 0; q < 6; q++) {
                    float4 s4 = *(const float4*)&S[(L + 32 * q) * SP + e];
#pragma unroll
                    for (int i = 0; i < 4; i++) {
                        sc[i][q] = fmaf(a4[i].x, s4.x, sc[i][q]);
                        sc[i][q] = fmaf(a4[i].y, s4.y, sc[i][q]);
                        sc[i][q] = fmaf(a4[i].z, s4.z, sc[i][q]);
                        sc[i][q] = fmaf(a4[i].w, s4.w, sc[i][q]);
                    }
                }
                float4 s6 = *(const float4*)&S[n6 * SP + e];
#pragma unroll
                for (int i = 0; i < 4; i++) {
                    sc[i][6] = fmaf(a4[i].x, s6.x, sc[i][6]);
                    sc[i][6] = fmaf(a4[i].y, s6.y, sc[i][6]);
                    sc[i][6] = fmaf(a4[i].z, s6.z, sc[i][6]);
                    sc[i][6] = fmaf(a4[i].w, s6.w, sc[i][6]);
                }
            }

            // softmax over 200, write att to SMEM
#pragma unroll
            for (int i = 0; i < 4; i++) {
                float m = sc[i][0];
#pragma unroll
                for (int q = 1; q < 6; q++) m = fmaxf(m, sc[i][q]);
                float v6 = (L < 8) ? sc[i][6] : -1e30f;
                m = fmaxf(m, v6);
#pragma unroll
                for (int o = 16; o > 0; o >>= 1)
                    m = fmaxf(m, __shfl_xor_sync(0xFFFFFFFFu, m, o));
                float ex[7], ssum = 0.0f;
#pragma unroll
                for (int q = 0; q < 6; q++) { ex[q] = __expf(sc[i][q] - m); ssum += ex[q]; }
                ex[6] = (L < 8) ? __expf(sc[i][6] - m) : 0.0f;
                ssum += ex[6];
#pragma unroll
                for (int o = 16; o > 0; o >>= 1)
                    ssum += __shfl_xor_sync(0xFFFFFFFFu, ssum, o);
                float inv = 1.0f / ssum;
                int tl = w * 4 + i;
#pragma unroll
                for (int q = 0; q < 6; q++) ATT[tl * 200 + L + 32 * q] = ex[q] * inv;
                if (L < 8) ATT[tl * 200 + 192 + L] = ex[6] * inv;
            }
            __syncwarp();

            // r[t][e] = sum_n att[t][n] * S[n][e]
#pragma unroll
            for (int i = 0; i < 4; i++) { r0[i] = 0.0f; r1[i] = 0.0f; }
            for (int n = 0; n < NKV; n += 4) {
                float s0a = S[(n + 0) * SP + L],      s1a = S[(n + 0) * SP + 32 + L];
                float s0b = S[(n + 1) * SP + L],      s1b = S[(n + 1) * SP + 32 + L];
                float s0c = S[(n + 2) * SP + L],      s1c = S[(n + 2) * SP + 32 + L];
                float s0d = S[(n + 3) * SP + L],      s1d = S[(n + 3) * SP + 32 + L];
#pragma unroll
                for (int i = 0; i < 4; i++) {
                    float4 a = *(const float4*)&ATT[(w * 4 + i) * 200 + n];
                    r0[i] = fmaf(a.x, s0a, r0[i]); r1[i] = fmaf(a.x, s1a, r1[i]);
                    r0[i] = fmaf(a.y, s0b, r0[i]); r1[i] = fmaf(a.y, s1b, r1[i]);
                    r0[i] = fmaf(a.z, s0c, r0[i]); r1[i] = fmaf(a.z, s1c, r1[i]);
                    r0[i] = fmaf(a.w, s0d, r0[i]); r1[i] = fmaf(a.w, s1d, r1[i]);
                }
            }
        }

        // LSTM cell: fused single e-loop, WH streamed once per warp.
        // Cell finish writes h_next + r (next iter's H) — last iter: h_next.
        {
            float z[4][8];
#pragma unroll
            for (int i = 0; i < 4; i++) {
                int grow = trow0 + w * 4 + i;
#pragma unroll
                for (int q = 0; q < 8; q++)
                    z[i][q] = g_pre_x[grow * 256 + L + 32 * q];
            }
            for (int e = 0; e < 64; e += 4) {
                float4 a4[4];
#pragma unroll
                for (int i = 0; i < 4; i++)
                    a4[i] = *(const float4*)&H[(w * 4 + i) * 64 + e];
#pragma unroll
                for (int q = 0; q < 8; q++) {
                    float4 w4 = *(const float4*)&WH[(L + 32 * q) * SP + e];
#pragma unroll
                    for (int i = 0; i < 4; i++) {
                        z[i][q] = fmaf(a4[i].x, w4.x, z[i][q]);
                        z[i][q] = fmaf(a4[i].y, w4.y, z[i][q]);
                        z[i][q] = fmaf(a4[i].z, w4.z, z[i][q]);
                        z[i][q] = fmaf(a4[i].w, w4.w, z[i][q]);
                    }
                }
            }
            __syncwarp();
#pragma unroll
            for (int i = 0; i < 4; i++) {
                int tl = w * 4 + i;
                float cc = sigf(z[i][2]) * c0[i] + sigf(z[i][0]) * tanhfast(z[i][4]);
                c0[i] = cc;
                float h0 = sigf(z[i][6]) * tanhfast(cc) + x0[i];
                float cc1 = sigf(z[i][3]) * c1[i] + sigf(z[i][1]) * tanhfast(z[i][5]);
                c1[i] = cc1;
                float h1 = sigf(z[i][7]) * tanhfast(cc1) + x1[i];
                if (not_last) { h0 += r0[i]; h1 += r1[i]; }
                H[tl * 64 + L] = h0;
                H[tl * 64 + 32 + L] = h1;
            }
            __syncwarp();
        }
    }

    // ---- final cosine-similarity softmax ----
    __syncthreads();
    for (int n = tid; n < NKV; n += 512) {
        float ss = 0.0f;
        for (int e = 0; e < 64; e += 4) {
            float4 v = *(const float4*)&S[n * SP + e];
            ss = fmaf(v.x, v.x, ss); ss = fmaf(v.y, v.y, ss);
            ss = fmaf(v.z, v.z, ss); ss = fmaf(v.w, v.w, ss);
        }
        SN[n] = sqrtf(ss);
    }
    __syncthreads();

    float sc[4][7];
#pragma unroll
    for (int i = 0; i < 4; i++)
#pragma unroll
        for (int q = 0; q < 7; q++) sc[i][q] = 0.0f;
    for (int e = 0; e < 64; e += 4) {
        float4 a4[4];
#pragma unroll
        for (int i = 0; i < 4; i++)
            a4[i] = *(const float4*)&H[(w * 4 + i) * 64 + e];
#pragma unroll
        for (int q = 0; q < 6; q++) {
            float4 s4 = *(const float4*)&S[(L + 32 * q) * SP + e];
#pragma unroll
            for (int i = 0; i < 4; i++) {
                sc[i][q] = fmaf(a4[i].x, s4.x, sc[i][q]);
                sc[i][q] = fmaf(a4[i].y, s4.y, sc[i][q]);
                sc[i][q] = fmaf(a4[i].z, s4.z, sc[i][q]);
                sc[i][q] = fmaf(a4[i].w, s4.w, sc[i][q]);
            }
        }
        float4 s6 = *(const float4*)&S[n6 * SP + e];
#pragma unroll
        for (int i = 0; i < 4; i++) {
            sc[i][6] = fmaf(a4[i].x, s6.x, sc[i][6]);
            sc[i][6] = fmaf(a4[i].y, s6.y, sc[i][6]);
            sc[i][6] = fmaf(a4[i].z, s6.z, sc[i][6]);
            sc[i][6] = fmaf(a4[i].w, s6.w, sc[i][6]);
        }
    }

#pragma unroll
    for (int i = 0; i < 4; i++) {
        int tl = w * 4 + i;
        float h0v = H[tl * 64 + L], h1v = H[tl * 64 + 32 + L];
        float p = h0v * h0v + h1v * h1v;
#pragma unroll
        for (int o = 16; o > 0; o >>= 1)
            p += __shfl_xor_sync(0xFFFFFFFFu, p, o);
        float tn = sqrtf(p);

#pragma unroll
        for (int q = 0; q < 6; q++) {
            float d = fmaxf(tn * SN[L + 32 * q], 1e-8f);
            sc[i][q] = __fdividef(sc[i][q], d);
        }
        {
            float d6 = fmaxf(tn * SN[n6], 1e-8f);
            sc[i][6] = __fdividef(sc[i][6], d6);
        }

        float m = sc[i][0];
#pragma unroll
        for (int q = 1; q < 6; q++) m = fmaxf(m, sc[i][q]);
        float v6 = (L < 8) ? sc[i][6] : -1e30f;
        m = fmaxf(m, v6);
#pragma unroll
        for (int o = 16; o > 0; o >>= 1)
            m = fmaxf(m, __shfl_xor_sync(0xFFFFFFFFu, m, o));
        float ex[7], ssum = 0.0f;
#pragma unroll
        for (int q = 0; q < 6; q++) { ex[q] = __expf(sc[i][q] - m); ssum += ex[q]; }
        ex[6] = (L < 8) ? __expf(sc[i][6] - m) : 0.0f;
        ssum += ex[6];
#pragma unroll
        for (int o = 16; o > 0; o >>= 1)
            ssum += __shfl_xor_sync(0xFFFFFFFFu, ssum, o);
        float inv = 1.0f / ssum;

        float* orow = out + (size_t)(trow0 + tl) * 200;
#pragma unroll
        for (int q = 0; q < 6; q++) orow[L + 32 * q] = ex[q] * inv;
        if (L < 8) orow[192 + L] = ex[6] * inv;
    }
}

// ---------------------------------------------------------------------------
extern "C" void kernel_launch(void* const* d_in, const int* in_sizes, int n_in,
                              void* d_out, int out_size)
{
    const int*   sup_tok = (const int*)d_in[0];
    const int*   tgt_tok = (const int*)d_in[1];
    const float* emb     = (const float*)d_in[2];
    const float* f_Wih   = (const float*)d_in[3];
    const float* f_Whh   = (const float*)d_in[4];
    const float* f_bih   = (const float*)d_in[5];
    const float* f_bhh   = (const float*)d_in[6];
    const float* gf_Wih  = (const float*)d_in[7];
    const float* gf_Whh  = (const float*)d_in[8];
    const float* gf_bih  = (const float*)d_in[9];
    const float* gf_bhh  = (const float*)d_in[10];
    const float* gb_Wih  = (const float*)d_in[11];
    const float* gb_Whh  = (const float*)d_in[12];
    const float* gb_bih  = (const float*)d_in[13];
    const float* gb_bhh  = (const float*)d_in[14];
    float* out = (float*)d_out;

    float *d_sup_enc, *d_tgt_enc, *d_pre_gf, *d_pre_gb, *d_pre_x;
    cudaGetSymbolAddress((void**)&d_sup_enc, g_sup_enc);
    cudaGetSymbolAddress((void**)&d_tgt_enc, g_tgt_enc);
    cudaGetSymbolAddress((void**)&d_pre_gf, g_pre_gf);
    cudaGetSymbolAddress((void**)&d_pre_gb, g_pre_gb);
    cudaGetSymbolAddress((void**)&d_pre_x, g_pre_x);

    // 1. embedding sums (support + target)
    embed_sum_kernel<<<(SUPROWS + TGTROWS) / 16, 256>>>(sup_tok, tgt_tok, emb);

    // 2. gf + gb gate-preactivation GEMMs (lstm's inputs)
    gemm_gfgb_kernel<<<400, 256>>>(d_sup_enc,
                                   gf_Wih, gf_bih, gf_bhh,
                                   gb_Wih, gb_bih, gb_bhh,
                                   d_pre_gf, d_pre_gb);

    // 3. merged: LSTM chains (blocks 0-127) + f-GEMM pre_x (blocks 128-255).
    lstm_gemmf_kernel<<<256, 256>>>(gf_Whh, gb_Whh,
                                    d_tgt_enc, f_Wih, f_bih, f_bhh,
                                    d_pre_x);

    // 4. fused attention loop + final output
    const int smem_bytes = (200 * SP + 256 * SP + 64 * 64 + 64 * 200 + 200) * 4;
    cudaFuncSetAttribute(attn_kernel, cudaFuncAttributeMaxDynamicSharedMemorySize,
                         smem_bytes);
    attn_kernel<<<BV * 2, 512, smem_bytes>>>(f_Whh, out);
}